// round 5
// baseline (speedup 1.0000x reference)
#include <cuda_runtime.h>
#include <math.h>

#define D 128
#define MAXN 100000

// Scratch (allocation-free: static __device__ arrays)
__device__ float g_agg[(size_t)MAXN * D];   // 51.2 MB aggregation buffer
__device__ float g_h[(size_t)MAXN * D];     // 51.2 MB hidden state h1
__device__ float g_deg[MAXN];               // in-degree (same for both layers)

// ---------------------------------------------------------------------------
// K0: zero agg/deg, copy change -> out[0:ND], zero out[ND:2ND] (jump target)
// ---------------------------------------------------------------------------
__global__ void k_init(const float* __restrict__ change, float* __restrict__ out, int n) {
    int i = blockIdx.x * blockDim.x + threadIdx.x;
    int nd4 = n * (D / 4);
    if (i < nd4) {
        float4 c = ((const float4*)change)[i];
        ((float4*)out)[i] = c;
        ((float4*)out)[(size_t)nd4 + i] = make_float4(0.f, 0.f, 0.f, 0.f);
        ((float4*)g_agg)[i] = make_float4(0.f, 0.f, 0.f, 0.f);
    }
    if (i < n) g_deg[i] = 0.f;
}

// ---------------------------------------------------------------------------
// Relational scatter: one warp per edge.
// ---------------------------------------------------------------------------
__global__ void k_scatter(const float* __restrict__ x, const float* __restrict__ rel,
                          const int* __restrict__ ei, const int* __restrict__ et,
                          int E, int addDeg) {
    int gw = (blockIdx.x * blockDim.x + threadIdx.x) >> 5;
    int lane = threadIdx.x & 31;
    if (gw >= E) return;
    int src = ei[gw];
    int dst = ei[E + gw];
    int t = et[gw];
    float4 xv = ((const float4*)x)[(size_t)src * (D / 4) + lane];
    float4 rv = ((const float4*)rel)[(size_t)t * (D / 4) + lane];
    float4 m = make_float4(xv.x * rv.x, xv.y * rv.y, xv.z * rv.z, xv.w * rv.w);
    float* p = g_agg + (size_t)dst * D + lane * 4;
    asm volatile("red.global.add.v4.f32 [%0], {%1,%2,%3,%4};"
                 :: "l"(p), "f"(m.x), "f"(m.y), "f"(m.z), "f"(m.w) : "memory");
    if (addDeg && lane == 0) atomicAdd(&g_deg[dst], 1.0f);
}

// ---------------------------------------------------------------------------
// Jump diffusion scatter: one warp per jump edge.
// ---------------------------------------------------------------------------
__global__ void k_jump(const float* __restrict__ emb, const float* __restrict__ w,
                       const int* __restrict__ ej, int EJ, float* __restrict__ outD) {
    int gw = (blockIdx.x * blockDim.x + threadIdx.x) >> 5;
    int lane = threadIdx.x & 31;
    if (gw >= EJ) return;
    int src = ej[gw];
    int dst = ej[EJ + gw];
    float wv = w[gw];
    float4 xv = ((const float4*)emb)[(size_t)src * (D / 4) + lane];
    float4 m = make_float4(wv * xv.x, wv * xv.y, wv * xv.z, wv * xv.w);
    float* p = outD + (size_t)dst * D + lane * 4;
    asm volatile("red.global.add.v4.f32 [%0], {%1,%2,%3,%4};"
                 :: "l"(p), "f"(m.x), "f"(m.y), "f"(m.z), "f"(m.w) : "memory");
}

// ---------------------------------------------------------------------------
// Fused layer GEMM (tf32 mma.sync), LDS.128 fragment-major B:
//   out[r] = x[r] + res * tanh( (agg[r]/max(deg,1)) @ W + x[r] @ Wl )
//            (+ jw * jump[r] for layer 2)
// smem holds one 128x128 weight in FRAGMENT-MAJOR order: per (ks,tig,nw,grp)
// a contiguous 64B block = 8 nt-tiles x {b0,b1}, with a (j+tig)&3 16B rotation
// for conflict-free LDS.128. Two passes (W then Wl) reuse the 64KB buffer ->
// 3 CTAs/SM. Warp tile 16x64, 8 warps = 64 rows x 128 cols per CTA.
// ---------------------------------------------------------------------------
#define SMEM_BYTES (64 * 1024)

__device__ __forceinline__ unsigned f2tf(float f) {
    unsigned u;
    asm("cvt.rna.tf32.f32 %0, %1;" : "=r"(u) : "f"(f));
    return u;
}

__device__ __forceinline__ void mma_tf32(float* c, unsigned a0, unsigned a1,
                                         unsigned a2, unsigned a3,
                                         unsigned b0, unsigned b1) {
    asm("mma.sync.aligned.m16n8k8.row.col.f32.tf32.tf32.f32 "
        "{%0,%1,%2,%3}, {%4,%5,%6,%7}, {%8,%9}, {%0,%1,%2,%3};"
        : "+f"(c[0]), "+f"(c[1]), "+f"(c[2]), "+f"(c[3])
        : "r"(a0), "r"(a1), "r"(a2), "r"(a3), "r"(b0), "r"(b1));
}

__global__ __launch_bounds__(256, 3)
void k_gemm(const float* __restrict__ x, const float* __restrict__ W,
            const float* __restrict__ Wl, const float* __restrict__ resp,
            const float* __restrict__ jwp, const float* __restrict__ jumpbuf,
            float* __restrict__ out, int n, int zeroAgg) {
    extern __shared__ unsigned sB[];  // 16384 u32, fragment-major

    const int tid = threadIdx.x;
    const int warp = tid >> 5, lane = tid & 31;
    const int grp = lane >> 2, tig = lane & 3;
    const int mw = warp >> 1;        // 0..3  (m tile)
    const int nw = warp & 1;         // 0..1  (n half)
    const int r0 = blockIdx.x * 64 + mw * 16 + grp;
    const int r1 = r0 + 8;
    const bool v0 = r0 < n, v1 = r1 < n;

    float rd0 = 0.f, rd1 = 0.f;
    if (v0) rd0 = 1.0f / fmaxf(g_deg[r0], 1.0f);
    if (v1) rd1 = 1.0f / fmaxf(g_deg[r1], 1.0f);

    float acc[8][4];
#pragma unroll
    for (int nt = 0; nt < 8; nt++)
#pragma unroll
        for (int q = 0; q < 4; q++) acc[nt][q] = 0.f;

#pragma unroll 1
    for (int pass = 0; pass < 2; pass++) {
        // Stage weight matrix (128x128 f32) into fragment-major tf32 smem.
        // Element B[k][c]: ks=k>>3, tg=k&3, p=(k&7)>>2; nw=c>>6, nt=(c>>3)&7,
        // gp=c&7; word w=nt*2+p, j=w>>2, m=w&3, rot=(j+tg)&3.
        const float* Wp = pass ? Wl : W;
        if (pass) __syncthreads();   // all warps done reading previous pass
        for (int i = tid; i < 128 * 32; i += 256) {
            int k = i >> 5, c4 = i & 31;
            float4 wv = ((const float4*)Wp)[i];
            int ks = k >> 3, tg = k & 3, p = (k & 7) >> 2;
            float vals[4] = {wv.x, wv.y, wv.z, wv.w};
#pragma unroll
            for (int q = 0; q < 4; q++) {
                int c = c4 * 4 + q;
                int cnw = c >> 6, nt = (c >> 3) & 7, gp = c & 7;
                int w = nt * 2 + p, j = w >> 2, m = w & 3;
                int rot = (j + tg) & 3;
                sB[((((ks * 4 + tg) * 2 + cnw) * 8 + gp) << 4) + rot * 4 + m] =
                    f2tf(vals[q]);
            }
        }
        __syncthreads();

        const float* Asrc = pass ? x : (const float*)g_agg;
        const float s0 = pass ? 1.f : rd0;
        const float s1 = pass ? 1.f : rd1;

#pragma unroll 4
        for (int ks = 0; ks < 16; ks++) {
            const int k0 = ks * 8 + tig;
            float f0 = v0 ? Asrc[(size_t)r0 * 128 + k0]     * s0 : 0.f;
            float f1 = v1 ? Asrc[(size_t)r1 * 128 + k0]     * s1 : 0.f;
            float f2 = v0 ? Asrc[(size_t)r0 * 128 + k0 + 4] * s0 : 0.f;
            float f3 = v1 ? Asrc[(size_t)r1 * 128 + k0 + 4] * s1 : 0.f;
            unsigned a0 = f2tf(f0), a1 = f2tf(f1), a2 = f2tf(f2), a3 = f2tf(f3);
            const unsigned* tb = sB + ((((ks * 4 + tig) * 2 + nw) * 8 + grp) << 4);
#pragma unroll
            for (int j = 0; j < 4; j++) {
                uint4 b = *(const uint4*)(tb + (((j + tig) & 3) << 2));
                mma_tf32(acc[2 * j],     a0, a1, a2, a3, b.x, b.y);
                mma_tf32(acc[2 * j + 1], a0, a1, a2, a3, b.z, b.w);
            }
        }
    }

    const float res = resp[0];
    const float jw = jwp ? jwp[0] : 0.f;
#pragma unroll
    for (int nt = 0; nt < 8; nt++) {
        const int c = nw * 64 + nt * 8 + tig * 2;
        if (v0) {
            float2 xv = *(const float2*)(x + (size_t)r0 * 128 + c);
            float o0 = xv.x + res * tanhf(acc[nt][0]);
            float o1 = xv.y + res * tanhf(acc[nt][1]);
            if (jumpbuf) {
                float2 jv = *(const float2*)(jumpbuf + (size_t)r0 * 128 + c);
                o0 += jw * jv.x; o1 += jw * jv.y;
            }
            *(float2*)(out + (size_t)r0 * 128 + c) = make_float2(o0, o1);
        }
        if (v1) {
            float2 xv = *(const float2*)(x + (size_t)r1 * 128 + c);
            float o0 = xv.x + res * tanhf(acc[nt][2]);
            float o1 = xv.y + res * tanhf(acc[nt][3]);
            if (jumpbuf) {
                float2 jv = *(const float2*)(jumpbuf + (size_t)r1 * 128 + c);
                o0 += jw * jv.x; o1 += jw * jv.y;
            }
            *(float2*)(out + (size_t)r1 * 128 + c) = make_float2(o0, o1);
        }
    }

    // Zero this warp's agg region for layer 2 (row x col-half exclusive)
    if (zeroAgg) {
        float4 z = make_float4(0.f, 0.f, 0.f, 0.f);
        if (v0) {
            float4* p = (float4*)(g_agg + (size_t)r0 * 128 + nw * 64 + tig * 16);
#pragma unroll
            for (int q = 0; q < 4; q++) p[q] = z;
        }
        if (v1) {
            float4* p = (float4*)(g_agg + (size_t)r1 * 128 + nw * 64 + tig * 16);
#pragma unroll
            for (int q = 0; q < 4; q++) p[q] = z;
        }
    }
}

// ---------------------------------------------------------------------------
// Launch sequence (graph-capturable: kernel launches only)
// ---------------------------------------------------------------------------
extern "C" void kernel_launch(void* const* d_in, const int* in_sizes, int n_in,
                              void* d_out, int out_size) {
    const float* emb    = (const float*)d_in[0];
    const float* change = (const float*)d_in[1];
    const float* W1     = (const float*)d_in[2];
    const float* Wl1    = (const float*)d_in[3];
    const float* rel1   = (const float*)d_in[4];
    const float* W2     = (const float*)d_in[5];
    const float* Wl2    = (const float*)d_in[6];
    const float* rel2   = (const float*)d_in[7];
    const float* res    = (const float*)d_in[8];
    const float* jw     = (const float*)d_in[9];
    const float* ewj    = (const float*)d_in[10];
    const int*   ei     = (const int*)d_in[11];
    const int*   et     = (const int*)d_in[12];
    const int*   ej     = (const int*)d_in[13];

    const int N  = in_sizes[0] / 128;
    const int E  = in_sizes[12];
    const int EJ = in_sizes[10];
    if (N <= 0 || E <= 0 || EJ <= 0) return;

    float* out  = (float*)d_out;
    float* outD = out + (size_t)N * 128;

    float* hptr = nullptr;
    cudaGetSymbolAddress((void**)&hptr, g_h);

    cudaFuncSetAttribute(k_gemm, cudaFuncAttributeMaxDynamicSharedMemorySize, SMEM_BYTES);

    const int nd4 = N * 32;
    k_init<<<(nd4 + 255) / 256, 256>>>(change, out, N);
    // layer-1 scatter (also accumulates deg)
    k_scatter<<<(E + 7) / 8, 256>>>(emb, rel1, ei, et, E, 1);
    // jump diffusion into dchange half (independent of convs)
    k_jump<<<(EJ + 7) / 8, 256>>>(emb, ewj, ej, EJ, outD);
    // layer 1: h1 = emb + res*tanh((agg/deg)@W1 + emb@Wloop1); zero agg for L2
    k_gemm<<<(N + 63) / 64, 256, SMEM_BYTES>>>(emb, W1, Wl1, res,
                                               nullptr, nullptr, hptr, N, 1);
    // layer-2 scatter (deg reused)
    k_scatter<<<(E + 7) / 8, 256>>>(hptr, rel2, ei, et, E, 0);
    // layer 2 + jump combine: dchange = h1 + res*tanh(...) + jw*jump
    k_gemm<<<(N + 63) / 64, 256, SMEM_BYTES>>>(hptr, W2, Wl2, res,
                                               jw, outD, outD, N, 0);
}

// round 7
// speedup vs baseline: 1.1541x; 1.1541x over previous
#include <cuda_runtime.h>
#include <math.h>

#define D 128
#define MAXN 100000

// Scratch (allocation-free: static __device__ arrays)
__device__ float g_agg[(size_t)MAXN * D];   // 51.2 MB aggregation buffer
__device__ float g_h[(size_t)MAXN * D];     // 51.2 MB hidden state h1
__device__ float g_deg[MAXN];               // in-degree (same for both layers)

// ---------------------------------------------------------------------------
// K0: zero agg/deg, copy change -> out[0:ND], zero out[ND:2ND] (jump target)
// ---------------------------------------------------------------------------
__global__ void k_init(const float* __restrict__ change, float* __restrict__ out, int n) {
    int i = blockIdx.x * blockDim.x + threadIdx.x;
    int nd4 = n * (D / 4);
    if (i < nd4) {
        float4 c = ((const float4*)change)[i];
        ((float4*)out)[i] = c;
        ((float4*)out)[(size_t)nd4 + i] = make_float4(0.f, 0.f, 0.f, 0.f);
        ((float4*)g_agg)[i] = make_float4(0.f, 0.f, 0.f, 0.f);
    }
    if (i < n) g_deg[i] = 0.f;
}

// ---------------------------------------------------------------------------
// Relational scatter: one warp per edge.
// ---------------------------------------------------------------------------
__global__ void k_scatter(const float* __restrict__ x, const float* __restrict__ rel,
                          const int* __restrict__ ei, const int* __restrict__ et,
                          int E, int addDeg) {
    int gw = (blockIdx.x * blockDim.x + threadIdx.x) >> 5;
    int lane = threadIdx.x & 31;
    if (gw >= E) return;
    int src = ei[gw];
    int dst = ei[E + gw];
    int t = et[gw];
    float4 xv = ((const float4*)x)[(size_t)src * (D / 4) + lane];
    float4 rv = ((const float4*)rel)[(size_t)t * (D / 4) + lane];
    float4 m = make_float4(xv.x * rv.x, xv.y * rv.y, xv.z * rv.z, xv.w * rv.w);
    float* p = g_agg + (size_t)dst * D + lane * 4;
    asm volatile("red.global.add.v4.f32 [%0], {%1,%2,%3,%4};"
                 :: "l"(p), "f"(m.x), "f"(m.y), "f"(m.z), "f"(m.w) : "memory");
    if (addDeg && lane == 0) atomicAdd(&g_deg[dst], 1.0f);
}

// ---------------------------------------------------------------------------
// Jump diffusion scatter: one warp per jump edge.
// ---------------------------------------------------------------------------
__global__ void k_jump(const float* __restrict__ emb, const float* __restrict__ w,
                       const int* __restrict__ ej, int EJ, float* __restrict__ outD) {
    int gw = (blockIdx.x * blockDim.x + threadIdx.x) >> 5;
    int lane = threadIdx.x & 31;
    if (gw >= EJ) return;
    int src = ej[gw];
    int dst = ej[EJ + gw];
    float wv = w[gw];
    float4 xv = ((const float4*)emb)[(size_t)src * (D / 4) + lane];
    float4 m = make_float4(wv * xv.x, wv * xv.y, wv * xv.z, wv * xv.w);
    float* p = outD + (size_t)dst * D + lane * 4;
    asm volatile("red.global.add.v4.f32 [%0], {%1,%2,%3,%4};"
                 :: "l"(p), "f"(m.x), "f"(m.y), "f"(m.z), "f"(m.w) : "memory");
}

// ---------------------------------------------------------------------------
// Fused layer GEMM (tf32 mma.sync), smem-staged A + swizzled B:
//   out[r] = x[r] + res * tanh( (agg[r]/max(deg,1)) @ W + x[r] @ Wl )
//            (+ jw * jump[r] for layer 2)
// B: 128x128 tf32, stride 128 words, col' = (c + 8*(k&3)) & 127 swizzle
//    -> bank = grp + 8*tig + const (conflict-free), 64KB, two passes (W, Wl).
// A: per 32-col chunk staged [64][32] f32 at stride 36 words (9.2KB),
//    coalesced float4 LDG, LDS bank = 4*grp + tig + 8*q (conflict-free).
// 64KB + 9.2KB = 73.2KB/CTA -> 3 CTAs/SM. Warp tile 16x64, 8 warps = 64x128.
// ---------------------------------------------------------------------------
#define A_STRIDE 36
#define SMEM_WORDS (128 * 128 + 64 * A_STRIDE)
#define SMEM_BYTES (SMEM_WORDS * 4)

__device__ __forceinline__ unsigned f2tf(float f) {
    unsigned u;
    asm("cvt.rna.tf32.f32 %0, %1;" : "=r"(u) : "f"(f));
    return u;
}

__device__ __forceinline__ void mma_tf32(float* c, unsigned a0, unsigned a1,
                                         unsigned a2, unsigned a3,
                                         unsigned b0, unsigned b1) {
    asm("mma.sync.aligned.m16n8k8.row.col.f32.tf32.tf32.f32 "
        "{%0,%1,%2,%3}, {%4,%5,%6,%7}, {%8,%9}, {%0,%1,%2,%3};"
        : "+f"(c[0]), "+f"(c[1]), "+f"(c[2]), "+f"(c[3])
        : "r"(a0), "r"(a1), "r"(a2), "r"(a3), "r"(b0), "r"(b1));
}

__global__ __launch_bounds__(256, 3)
void k_gemm(const float* __restrict__ x, const float* __restrict__ W,
            const float* __restrict__ Wl, const float* __restrict__ resp,
            const float* __restrict__ jwp, const float* __restrict__ jumpbuf,
            float* __restrict__ out, int n, int zeroAgg) {
    extern __shared__ unsigned sB[];            // B: words [0, 16384)
    float* sAf = (float*)(sB + 128 * 128);      // A: words [16384, +2304)

    const int tid = threadIdx.x;
    const int warp = tid >> 5, lane = tid & 31;
    const int grp = lane >> 2, tig = lane & 3;
    const int mw = warp >> 1;        // 0..3  (m tile)
    const int nw = warp & 1;         // 0..1  (n half)
    const int rl0 = mw * 16 + grp;   // local row (0..63)
    const int rl1 = rl0 + 8;
    const int r0 = blockIdx.x * 64 + rl0;
    const int r1 = r0 + 8;
    const bool v0 = r0 < n, v1 = r1 < n;

    float rd0 = 0.f, rd1 = 0.f;
    if (v0) rd0 = 1.0f / fmaxf(g_deg[r0], 1.0f);
    if (v1) rd1 = 1.0f / fmaxf(g_deg[r1], 1.0f);

    float acc[8][4];
#pragma unroll
    for (int nt = 0; nt < 8; nt++)
#pragma unroll
        for (int q = 0; q < 4; q++) acc[nt][q] = 0.f;

    const int bbase = nw * 64 + grp + tig * 8;  // B col swizzle base for this lane

#pragma unroll 1
    for (int pass = 0; pass < 2; pass++) {
        // ---- Stage weight matrix (128x128 f32 -> swizzled tf32 smem) ----
        const float* Wp = pass ? Wl : W;
        if (pass) __syncthreads();   // all warps done reading pass-0 B/A
        for (int i = tid; i < 128 * 32; i += 256) {
            int k = i >> 5, c4 = i & 31;
            float4 wv = ((const float4*)Wp)[i];
            int off = (c4 * 4 + ((k & 3) << 3)) & 127;
            unsigned* s = sB + k * 128 + off;
            s[0] = f2tf(wv.x); s[1] = f2tf(wv.y);
            s[2] = f2tf(wv.z); s[3] = f2tf(wv.w);
        }

        const float* Asrc = pass ? x : (const float*)g_agg;
        const float s0 = pass ? 1.f : rd0;
        const float s1 = pass ? 1.f : rd1;

#pragma unroll 1
        for (int chunk = 0; chunk < 4; chunk++) {
            __syncthreads();  // B staged / previous A chunk consumed
            // ---- Stage A[64][32] chunk, coalesced float4 ----
#pragma unroll
            for (int t = 0; t < 2; t++) {
                int j = tid + t * 256;            // 0..511
                int row = j >> 3, c4 = j & 7;
                int grow = blockIdx.x * 64 + row;
                float4 v = make_float4(0.f, 0.f, 0.f, 0.f);
                if (grow < n)
                    v = ((const float4*)Asrc)[(size_t)grow * 32 + chunk * 8 + c4];
                *(float4*)(sAf + row * A_STRIDE + c4 * 4) = v;
            }
            __syncthreads();

#pragma unroll
            for (int q = 0; q < 4; q++) {
                const int ks = chunk * 4 + q;
                float f0 = sAf[rl0 * A_STRIDE + q * 8 + tig]     * s0;
                float f1 = sAf[rl1 * A_STRIDE + q * 8 + tig]     * s1;
                float f2 = sAf[rl0 * A_STRIDE + q * 8 + tig + 4] * s0;
                float f3 = sAf[rl1 * A_STRIDE + q * 8 + tig + 4] * s1;
                unsigned a0 = f2tf(f0), a1 = f2tf(f1), a2 = f2tf(f2), a3 = f2tf(f3);
                const unsigned* pb = sB + (ks * 8 + tig) * 128;
#pragma unroll
                for (int nt = 0; nt < 8; nt++) {
                    int c = (bbase + nt * 8) & 127;
                    unsigned b0 = pb[c];
                    unsigned b1 = pb[512 + c];
                    mma_tf32(acc[nt], a0, a1, a2, a3, b0, b1);
                }
            }
        }
    }

    const float res = resp[0];
    const float jw = jwp ? jwp[0] : 0.f;
#pragma unroll
    for (int nt = 0; nt < 8; nt++) {
        const int c = nw * 64 + nt * 8 + tig * 2;
        if (v0) {
            float2 xv = *(const float2*)(x + (size_t)r0 * 128 + c);
            float o0 = xv.x + res * tanhf(acc[nt][0]);
            float o1 = xv.y + res * tanhf(acc[nt][1]);
            if (jumpbuf) {
                float2 jv = *(const float2*)(jumpbuf + (size_t)r0 * 128 + c);
                o0 += jw * jv.x; o1 += jw * jv.y;
            }
            *(float2*)(out + (size_t)r0 * 128 + c) = make_float2(o0, o1);
        }
        if (v1) {
            float2 xv = *(const float2*)(x + (size_t)r1 * 128 + c);
            float o0 = xv.x + res * tanhf(acc[nt][2]);
            float o1 = xv.y + res * tanhf(acc[nt][3]);
            if (jumpbuf) {
                float2 jv = *(const float2*)(jumpbuf + (size_t)r1 * 128 + c);
                o0 += jw * jv.x; o1 += jw * jv.y;
            }
            *(float2*)(out + (size_t)r1 * 128 + c) = make_float2(o0, o1);
        }
    }

    // Zero this warp's agg region for layer 2 (row x col-half exclusive)
    if (zeroAgg) {
        float4 z = make_float4(0.f, 0.f, 0.f, 0.f);
        if (v0) {
            float4* p = (float4*)(g_agg + (size_t)r0 * 128 + nw * 64 + tig * 16);
#pragma unroll
            for (int q = 0; q < 4; q++) p[q] = z;
        }
        if (v1) {
            float4* p = (float4*)(g_agg + (size_t)r1 * 128 + nw * 64 + tig * 16);
#pragma unroll
            for (int q = 0; q < 4; q++) p[q] = z;
        }
    }
}

// ---------------------------------------------------------------------------
// Launch sequence (graph-capturable: kernel launches only)
// ---------------------------------------------------------------------------
extern "C" void kernel_launch(void* const* d_in, const int* in_sizes, int n_in,
                              void* d_out, int out_size) {
    const float* emb    = (const float*)d_in[0];
    const float* change = (const float*)d_in[1];
    const float* W1     = (const float*)d_in[2];
    const float* Wl1    = (const float*)d_in[3];
    const float* rel1   = (const float*)d_in[4];
    const float* W2     = (const float*)d_in[5];
    const float* Wl2    = (const float*)d_in[6];
    const float* rel2   = (const float*)d_in[7];
    const float* res    = (const float*)d_in[8];
    const float* jw     = (const float*)d_in[9];
    const float* ewj    = (const float*)d_in[10];
    const int*   ei     = (const int*)d_in[11];
    const int*   et     = (const int*)d_in[12];
    const int*   ej     = (const int*)d_in[13];

    const int N  = in_sizes[0] / 128;
    const int E  = in_sizes[12];
    const int EJ = in_sizes[10];
    if (N <= 0 || E <= 0 || EJ <= 0) return;

    float* out  = (float*)d_out;
    float* outD = out + (size_t)N * 128;

    float* hptr = nullptr;
    cudaGetSymbolAddress((void**)&hptr, g_h);

    cudaFuncSetAttribute(k_gemm, cudaFuncAttributeMaxDynamicSharedMemorySize, SMEM_BYTES);

    const int nd4 = N * 32;
    k_init<<<(nd4 + 255) / 256, 256>>>(change, out, N);
    // layer-1 scatter (also accumulates deg)
    k_scatter<<<(E + 7) / 8, 256>>>(emb, rel1, ei, et, E, 1);
    // jump diffusion into dchange half (independent of convs)
    k_jump<<<(EJ + 7) / 8, 256>>>(emb, ewj, ej, EJ, outD);
    // layer 1: h1 = emb + res*tanh((agg/deg)@W1 + emb@Wloop1); zero agg for L2
    k_gemm<<<(N + 63) / 64, 256, SMEM_BYTES>>>(emb, W1, Wl1, res,
                                               nullptr, nullptr, hptr, N, 1);
    // layer-2 scatter (deg reused)
    k_scatter<<<(E + 7) / 8, 256>>>(hptr, rel2, ei, et, E, 0);
    // layer 2 + jump combine: dchange = h1 + res*tanh(...) + jw*jump
    k_gemm<<<(N + 63) / 64, 256, SMEM_BYTES>>>(hptr, W2, Wl2, res,
                                               jw, outD, outD, N, 0);
}

// round 8
// speedup vs baseline: 1.1974x; 1.0375x over previous
#include <cuda_runtime.h>
#include <math.h>

#define D 128
#define MAXN 100000

// Scratch (allocation-free: static __device__ arrays)
__device__ float g_agg[(size_t)MAXN * D];   // 51.2 MB aggregation buffer
__device__ float g_h[(size_t)MAXN * D];     // 51.2 MB hidden state h1
__device__ float g_deg[MAXN];               // in-degree (same for both layers)

// ---------------------------------------------------------------------------
// K0: zero agg/deg, copy change -> out[0:ND], zero out[ND:2ND] (jump target)
// ---------------------------------------------------------------------------
__global__ void k_init(const float* __restrict__ change, float* __restrict__ out, int n) {
    int i = blockIdx.x * blockDim.x + threadIdx.x;
    int nd4 = n * (D / 4);
    if (i < nd4) {
        float4 c = ((const float4*)change)[i];
        ((float4*)out)[i] = c;
        ((float4*)out)[(size_t)nd4 + i] = make_float4(0.f, 0.f, 0.f, 0.f);
        ((float4*)g_agg)[i] = make_float4(0.f, 0.f, 0.f, 0.f);
    }
    if (i < n) g_deg[i] = 0.f;
}

// ---------------------------------------------------------------------------
// Relational scatter: one warp per edge.
// ---------------------------------------------------------------------------
__global__ void k_scatter(const float* __restrict__ x, const float* __restrict__ rel,
                          const int* __restrict__ ei, const int* __restrict__ et,
                          int E, int addDeg) {
    int gw = (blockIdx.x * blockDim.x + threadIdx.x) >> 5;
    int lane = threadIdx.x & 31;
    if (gw >= E) return;
    int src = ei[gw];
    int dst = ei[E + gw];
    int t = et[gw];
    float4 xv = ((const float4*)x)[(size_t)src * (D / 4) + lane];
    float4 rv = ((const float4*)rel)[(size_t)t * (D / 4) + lane];
    float4 m = make_float4(xv.x * rv.x, xv.y * rv.y, xv.z * rv.z, xv.w * rv.w);
    float* p = g_agg + (size_t)dst * D + lane * 4;
    asm volatile("red.global.add.v4.f32 [%0], {%1,%2,%3,%4};"
                 :: "l"(p), "f"(m.x), "f"(m.y), "f"(m.z), "f"(m.w) : "memory");
    if (addDeg && lane == 0) atomicAdd(&g_deg[dst], 1.0f);
}

// ---------------------------------------------------------------------------
// Jump diffusion scatter: one warp per jump edge.
// ---------------------------------------------------------------------------
__global__ void k_jump(const float* __restrict__ emb, const float* __restrict__ w,
                       const int* __restrict__ ej, int EJ, float* __restrict__ outD) {
    int gw = (blockIdx.x * blockDim.x + threadIdx.x) >> 5;
    int lane = threadIdx.x & 31;
    if (gw >= EJ) return;
    int src = ej[gw];
    int dst = ej[EJ + gw];
    float wv = w[gw];
    float4 xv = ((const float4*)emb)[(size_t)src * (D / 4) + lane];
    float4 m = make_float4(wv * xv.x, wv * xv.y, wv * xv.z, wv * xv.w);
    float* p = outD + (size_t)dst * D + lane * 4;
    asm volatile("red.global.add.v4.f32 [%0], {%1,%2,%3,%4};"
                 :: "l"(p), "f"(m.x), "f"(m.y), "f"(m.z), "f"(m.w) : "memory");
}

// ---------------------------------------------------------------------------
// Fused layer GEMM (tf32 mma.sync):
//   out[r] = x[r] + res * tanh( (agg[r]/max(deg,1)) @ W + x[r] @ Wl )
//            (+ jw * jump[r] for layer 2)
// 32x32 warp tiles (2m x 4n), pre-scaled tf32 A in smem, register-prefetch
// pipelined A chunks (flat 8-chunk loop, pass boundary at chunk 4).
// B: 128x128 tf32, col' = (c + 8*(k&3)) & 127 swizzle, conflict-free.
// A: [64][32] chunk at stride 36 words, pre-scaled tf32, conflict-free.
// 64KB + 9.2KB = 73.2KB/CTA -> 3 CTAs/SM.
// ---------------------------------------------------------------------------
#define A_STRIDE 36
#define SMEM_WORDS (128 * 128 + 64 * A_STRIDE)
#define SMEM_BYTES (SMEM_WORDS * 4)

__device__ __forceinline__ unsigned f2tf(float f) {
    unsigned u;
    asm("cvt.rna.tf32.f32 %0, %1;" : "=r"(u) : "f"(f));
    return u;
}

__device__ __forceinline__ void mma_tf32(float* c, unsigned a0, unsigned a1,
                                         unsigned a2, unsigned a3,
                                         unsigned b0, unsigned b1) {
    asm("mma.sync.aligned.m16n8k8.row.col.f32.tf32.tf32.f32 "
        "{%0,%1,%2,%3}, {%4,%5,%6,%7}, {%8,%9}, {%0,%1,%2,%3};"
        : "+f"(c[0]), "+f"(c[1]), "+f"(c[2]), "+f"(c[3])
        : "r"(a0), "r"(a1), "r"(a2), "r"(a3), "r"(b0), "r"(b1));
}

__global__ __launch_bounds__(256, 3)
void k_gemm(const float* __restrict__ x, const float* __restrict__ W,
            const float* __restrict__ Wl, const float* __restrict__ resp,
            const float* __restrict__ jwp, const float* __restrict__ jumpbuf,
            float* __restrict__ out, int n, int zeroAgg) {
    extern __shared__ unsigned sB[];            // B: words [0, 16384)
    unsigned* sA = sB + 128 * 128;              // A: pre-scaled tf32, stride 36

    const int tid = threadIdx.x;
    const int warp = tid >> 5, lane = tid & 31;
    const int grp = lane >> 2, tig = lane & 3;
    const int mw = warp >> 2;        // 0..1  (m half: 32 rows)
    const int nw = warp & 3;         // 0..3  (n quarter: 32 cols)
    const int rbase = mw * 32 + grp; // local row of m-tile 0 pair

    // Staging identity: rows sr0, sr0+32; cols c4*4 within 32-col chunk
    const int sr0 = tid >> 3, c4 = tid & 7;
    const int sr1 = sr0 + 32;
    const int grow0 = blockIdx.x * 64 + sr0;
    const int grow1 = grow0 + 32;
    const bool gv0 = grow0 < n, gv1 = grow1 < n;
    float rds0 = 0.f, rds1 = 0.f;
    if (gv0) rds0 = 1.0f / fmaxf(g_deg[grow0], 1.0f);
    if (gv1) rds1 = 1.0f / fmaxf(g_deg[grow1], 1.0f);

    float acc[8][4];                 // [mt*4 + nt][4]
#pragma unroll
    for (int i = 0; i < 8; i++)
#pragma unroll
        for (int q = 0; q < 4; q++) acc[i][q] = 0.f;

    const int bbase = nw * 32 + grp + tig * 8;  // B swizzled col base

    // Preload chunk 0 (Asrc = agg)
    float4 pv0 = make_float4(0.f, 0.f, 0.f, 0.f);
    float4 pv1 = make_float4(0.f, 0.f, 0.f, 0.f);
    if (gv0) pv0 = ((const float4*)g_agg)[(size_t)grow0 * 32 + c4];
    if (gv1) pv1 = ((const float4*)g_agg)[(size_t)grow1 * 32 + c4];

#pragma unroll 1
    for (int c = 0; c < 8; c++) {
        __syncthreads();   // prev chunk consumed / (c==4) pass-0 B+A done

        // Stage B at pass starts
        if (c == 0 || c == 4) {
            const float* Wp = (c == 0) ? W : Wl;
            for (int i = tid; i < 128 * 32; i += 256) {
                int k = i >> 5, cc4 = i & 31;
                float4 wv = ((const float4*)Wp)[i];
                int off = (cc4 * 4 + ((k & 3) << 3)) & 127;
                unsigned* s = sB + k * 128 + off;
                s[0] = f2tf(wv.x); s[1] = f2tf(wv.y);
                s[2] = f2tf(wv.z); s[3] = f2tf(wv.w);
            }
        }

        // Store prefetched A chunk, pre-scaled, as tf32 bits
        {
            const float s0 = (c < 4) ? rds0 : 1.f;
            const float s1 = (c < 4) ? rds1 : 1.f;
            uint4 u0 = make_uint4(f2tf(pv0.x * s0), f2tf(pv0.y * s0),
                                  f2tf(pv0.z * s0), f2tf(pv0.w * s0));
            uint4 u1 = make_uint4(f2tf(pv1.x * s1), f2tf(pv1.y * s1),
                                  f2tf(pv1.z * s1), f2tf(pv1.w * s1));
            *(uint4*)(sA + sr0 * A_STRIDE + c4 * 4) = u0;
            *(uint4*)(sA + sr1 * A_STRIDE + c4 * 4) = u1;
        }

        // Prefetch next chunk (overlaps with mma loop below)
        if (c < 7) {
            const float* An = (c + 1 < 4) ? (const float*)g_agg : x;
            const int ch = (c + 1) & 3;
            pv0 = make_float4(0.f, 0.f, 0.f, 0.f);
            pv1 = make_float4(0.f, 0.f, 0.f, 0.f);
            if (gv0) pv0 = ((const float4*)An)[(size_t)grow0 * 32 + ch * 8 + c4];
            if (gv1) pv1 = ((const float4*)An)[(size_t)grow1 * 32 + ch * 8 + c4];
        }
        __syncthreads();   // A (and B) staged

#pragma unroll
        for (int q = 0; q < 4; q++) {
            const int kb = ((c & 3) * 4 + q) * 8 + tig;   // k row within pass
            const int ac = q * 8 + tig;
            // A fragments for both m-tiles (pre-scaled tf32)
            unsigned a00 = sA[(rbase)      * A_STRIDE + ac];
            unsigned a01 = sA[(rbase + 8)  * A_STRIDE + ac];
            unsigned a02 = sA[(rbase)      * A_STRIDE + ac + 4];
            unsigned a03 = sA[(rbase + 8)  * A_STRIDE + ac + 4];
            unsigned a10 = sA[(rbase + 16) * A_STRIDE + ac];
            unsigned a11 = sA[(rbase + 24) * A_STRIDE + ac];
            unsigned a12 = sA[(rbase + 16) * A_STRIDE + ac + 4];
            unsigned a13 = sA[(rbase + 24) * A_STRIDE + ac + 4];
            const unsigned* pb = sB + kb * 128;
#pragma unroll
            for (int nt = 0; nt < 4; nt++) {
                int col = (bbase + nt * 8) & 127;
                unsigned b0 = pb[col];
                unsigned b1 = pb[512 + col];
                mma_tf32(acc[nt],     a00, a01, a02, a03, b0, b1);
                mma_tf32(acc[4 + nt], a10, a11, a12, a13, b0, b1);
            }
        }
    }

    const float res = resp[0];
    const float jw = jwp ? jwp[0] : 0.f;
#pragma unroll
    for (int mt = 0; mt < 2; mt++) {
        const int r0 = blockIdx.x * 64 + mw * 32 + mt * 16 + grp;
        const int r1 = r0 + 8;
        const bool v0 = r0 < n, v1 = r1 < n;
#pragma unroll
        for (int nt = 0; nt < 4; nt++) {
            const int cc = nw * 32 + nt * 8 + tig * 2;
            const float* a = acc[mt * 4 + nt];
            if (v0) {
                float2 xv = *(const float2*)(x + (size_t)r0 * 128 + cc);
                float o0 = xv.x + res * tanhf(a[0]);
                float o1 = xv.y + res * tanhf(a[1]);
                if (jumpbuf) {
                    float2 jv = *(const float2*)(jumpbuf + (size_t)r0 * 128 + cc);
                    o0 += jw * jv.x; o1 += jw * jv.y;
                }
                *(float2*)(out + (size_t)r0 * 128 + cc) = make_float2(o0, o1);
            }
            if (v1) {
                float2 xv = *(const float2*)(x + (size_t)r1 * 128 + cc);
                float o0 = xv.x + res * tanhf(a[2]);
                float o1 = xv.y + res * tanhf(a[3]);
                if (jumpbuf) {
                    float2 jv = *(const float2*)(jumpbuf + (size_t)r1 * 128 + cc);
                    o0 += jw * jv.x; o1 += jw * jv.y;
                }
                *(float2*)(out + (size_t)r1 * 128 + cc) = make_float2(o0, o1);
            }
        }
    }

    // Zero this warp's agg region for layer 2 (32 rows x 32 cols, exclusive)
    if (zeroAgg) {
        int zr = blockIdx.x * 64 + mw * 32 + lane;
        if (zr < n) {
            float4* p = (float4*)(g_agg + (size_t)zr * 128 + nw * 32);
            float4 z = make_float4(0.f, 0.f, 0.f, 0.f);
#pragma unroll
            for (int q = 0; q < 8; q++) p[q] = z;
        }
    }
}

// ---------------------------------------------------------------------------
// Launch sequence (graph-capturable: kernel launches only)
// ---------------------------------------------------------------------------
extern "C" void kernel_launch(void* const* d_in, const int* in_sizes, int n_in,
                              void* d_out, int out_size) {
    const float* emb    = (const float*)d_in[0];
    const float* change = (const float*)d_in[1];
    const float* W1     = (const float*)d_in[2];
    const float* Wl1    = (const float*)d_in[3];
    const float* rel1   = (const float*)d_in[4];
    const float* W2     = (const float*)d_in[5];
    const float* Wl2    = (const float*)d_in[6];
    const float* rel2   = (const float*)d_in[7];
    const float* res    = (const float*)d_in[8];
    const float* jw     = (const float*)d_in[9];
    const float* ewj    = (const float*)d_in[10];
    const int*   ei     = (const int*)d_in[11];
    const int*   et     = (const int*)d_in[12];
    const int*   ej     = (const int*)d_in[13];

    const int N  = in_sizes[0] / 128;
    const int E  = in_sizes[12];
    const int EJ = in_sizes[10];
    if (N <= 0 || E <= 0 || EJ <= 0) return;

    float* out  = (float*)d_out;
    float* outD = out + (size_t)N * 128;

    float* hptr = nullptr;
    cudaGetSymbolAddress((void**)&hptr, g_h);

    cudaFuncSetAttribute(k_gemm, cudaFuncAttributeMaxDynamicSharedMemorySize, SMEM_BYTES);

    const int nd4 = N * 32;
    k_init<<<(nd4 + 255) / 256, 256>>>(change, out, N);
    // layer-1 scatter (also accumulates deg)
    k_scatter<<<(E + 7) / 8, 256>>>(emb, rel1, ei, et, E, 1);
    // jump diffusion into dchange half (independent of convs)
    k_jump<<<(EJ + 7) / 8, 256>>>(emb, ewj, ej, EJ, outD);
    // layer 1: h1 = emb + res*tanh((agg/deg)@W1 + emb@Wloop1); zero agg for L2
    k_gemm<<<(N + 63) / 64, 256, SMEM_BYTES>>>(emb, W1, Wl1, res,
                                               nullptr, nullptr, hptr, N, 1);
    // layer-2 scatter (deg reused)
    k_scatter<<<(E + 7) / 8, 256>>>(hptr, rel2, ei, et, E, 0);
    // layer 2 + jump combine: dchange = h1 + res*tanh(...) + jw*jump
    k_gemm<<<(N + 63) / 64, 256, SMEM_BYTES>>>(hptr, W2, Wl2, res,
                                               jw, outD, outD, N, 0);
}

// round 10
// speedup vs baseline: 1.3039x; 1.0890x over previous
#include <cuda_runtime.h>
#include <math.h>

#define D 128
#define MAXN 100000

// Scratch (allocation-free: static __device__ arrays)
__device__ float g_agg[(size_t)MAXN * D];   // 51.2 MB aggregation buffer
__device__ float g_h[(size_t)MAXN * D];     // 51.2 MB hidden state h1
__device__ float g_deg[MAXN];               // in-degree (same for both layers)

// ---------------------------------------------------------------------------
// K0: zero agg/deg, copy change -> out[0:ND], zero out[ND:2ND] (jump target)
// ---------------------------------------------------------------------------
__global__ void k_init(const float* __restrict__ change, float* __restrict__ out, int n) {
    int i = blockIdx.x * blockDim.x + threadIdx.x;
    int nd4 = n * (D / 4);
    if (i < nd4) {
        float4 c = ((const float4*)change)[i];
        ((float4*)out)[i] = c;
        ((float4*)out)[(size_t)nd4 + i] = make_float4(0.f, 0.f, 0.f, 0.f);
        ((float4*)g_agg)[i] = make_float4(0.f, 0.f, 0.f, 0.f);
    }
    if (i < n) g_deg[i] = 0.f;
}

// ---------------------------------------------------------------------------
// Relational scatter: one warp per edge.
// ---------------------------------------------------------------------------
__global__ void k_scatter(const float* __restrict__ x, const float* __restrict__ rel,
                          const int* __restrict__ ei, const int* __restrict__ et,
                          int E, int addDeg) {
    int gw = (blockIdx.x * blockDim.x + threadIdx.x) >> 5;
    int lane = threadIdx.x & 31;
    if (gw >= E) return;
    int src = ei[gw];
    int dst = ei[E + gw];
    int t = et[gw];
    float4 xv = ((const float4*)x)[(size_t)src * (D / 4) + lane];
    float4 rv = ((const float4*)rel)[(size_t)t * (D / 4) + lane];
    float4 m = make_float4(xv.x * rv.x, xv.y * rv.y, xv.z * rv.z, xv.w * rv.w);
    float* p = g_agg + (size_t)dst * D + lane * 4;
    asm volatile("red.global.add.v4.f32 [%0], {%1,%2,%3,%4};"
                 :: "l"(p), "f"(m.x), "f"(m.y), "f"(m.z), "f"(m.w) : "memory");
    if (addDeg && lane == 0) atomicAdd(&g_deg[dst], 1.0f);
}

// ---------------------------------------------------------------------------
// Jump diffusion scatter: one warp per jump edge.
// ---------------------------------------------------------------------------
__global__ void k_jump(const float* __restrict__ emb, const float* __restrict__ w,
                       const int* __restrict__ ej, int EJ, float* __restrict__ outD) {
    int gw = (blockIdx.x * blockDim.x + threadIdx.x) >> 5;
    int lane = threadIdx.x & 31;
    if (gw >= EJ) return;
    int src = ej[gw];
    int dst = ej[EJ + gw];
    float wv = w[gw];
    float4 xv = ((const float4*)emb)[(size_t)src * (D / 4) + lane];
    float4 m = make_float4(wv * xv.x, wv * xv.y, wv * xv.z, wv * xv.w);
    float* p = outD + (size_t)dst * D + lane * 4;
    asm volatile("red.global.add.v4.f32 [%0], {%1,%2,%3,%4};"
                 :: "l"(p), "f"(m.x), "f"(m.y), "f"(m.z), "f"(m.w) : "memory");
}

// ---------------------------------------------------------------------------
// Fused layer GEMM (bf16 mma.sync m16n8k16):
//   out[r] = x[r] + res * tanh( (agg[r]/max(deg,1)) @ W + x[r] @ Wl )
//            (+ jw * jump[r] for layer 2)
// 32x32 warp tiles (2m x 4n). B: one weight at a time as bf16x2 words,
// 64 word-rows x 128 cols, col' = (c + 8*(kw&3)) & 127 swizzle (conflict-
// free: kr&3 == tig for both b0/b1 rows). A: [64][16] bf16x2 words per
// 32-k chunk, stride 20 words (banks 20*grp+8q+tig: conflict-free),
// pre-scaled at staging. Register-prefetch pipelined, flat 8-chunk loop.
// smem = 32KB (B) + 5KB (A) -> 3 CTAs/SM (reg-capped).
// ---------------------------------------------------------------------------
#define A_STRIDE 20
#define SMEM_WORDS (64 * 128 + 64 * A_STRIDE)
#define SMEM_BYTES (SMEM_WORDS * 4)

__device__ __forceinline__ unsigned pack_bf16(float lo, float hi) {
    unsigned r;
    asm("cvt.rn.bf16x2.f32 %0, %1, %2;" : "=r"(r) : "f"(hi), "f"(lo));
    return r;
}

__device__ __forceinline__ void mma_bf16(float* c, unsigned a0, unsigned a1,
                                         unsigned a2, unsigned a3,
                                         unsigned b0, unsigned b1) {
    asm("mma.sync.aligned.m16n8k16.row.col.f32.bf16.bf16.f32 "
        "{%0,%1,%2,%3}, {%4,%5,%6,%7}, {%8,%9}, {%0,%1,%2,%3};"
        : "+f"(c[0]), "+f"(c[1]), "+f"(c[2]), "+f"(c[3])
        : "r"(a0), "r"(a1), "r"(a2), "r"(a3), "r"(b0), "r"(b1));
}

__global__ __launch_bounds__(256, 3)
void k_gemm(const float* __restrict__ x, const float* __restrict__ W,
            const float* __restrict__ Wl, const float* __restrict__ resp,
            const float* __restrict__ jwp, const float* __restrict__ jumpbuf,
            float* __restrict__ out, int n, int zeroAgg) {
    extern __shared__ unsigned sB[];            // B: words [0, 8192) bf16x2
    unsigned* sA = sB + 64 * 128;               // A: [64][20] bf16x2 words

    const int tid = threadIdx.x;
    const int warp = tid >> 5, lane = tid & 31;
    const int grp = lane >> 2, tig = lane & 3;
    const int mw = warp >> 2;        // 0..1  (m half: 32 rows)
    const int nw = warp & 3;         // 0..3  (n quarter: 32 cols)
    const int rbase = mw * 32 + grp;

    // A staging identity: 1 row per thread, 4 words (8 f32 cols) per chunk
    const int srow = tid >> 2, wq = tid & 3;
    const int grow = blockIdx.x * 64 + srow;
    const bool gv = grow < n;
    float rds = 0.f;
    if (gv) rds = 1.0f / fmaxf(g_deg[grow], 1.0f);

    float acc[8][4];                 // [mt*4 + nt][4]
#pragma unroll
    for (int i = 0; i < 8; i++)
#pragma unroll
        for (int q = 0; q < 4; q++) acc[i][q] = 0.f;

    const int bbase = nw * 32 + grp + tig * 8;  // swizzled B col base

    // Preload chunk 0 (Asrc = agg): 2 consecutive float4 (8 f32)
    float4 pva = make_float4(0.f, 0.f, 0.f, 0.f);
    float4 pvb = make_float4(0.f, 0.f, 0.f, 0.f);
    if (gv) {
        pva = ((const float4*)g_agg)[(size_t)grow * 32 + wq * 2];
        pvb = ((const float4*)g_agg)[(size_t)grow * 32 + wq * 2 + 1];
    }

#pragma unroll 1
    for (int c = 0; c < 8; c++) {
        __syncthreads();   // prev chunk consumed / (c==4) pass-0 B done

        // Stage B (bf16x2 word-pairs along k) at pass starts
        if (c == 0 || c == 4) {
            const float* Wp = (c == 0) ? W : Wl;
#pragma unroll
            for (int t = 0; t < 8; t++) {
                int j = tid + t * 256;          // 0..2047
                int kw = j >> 5, c4 = j & 31;   // word-row, col quad
                float4 w0 = ((const float4*)Wp)[(2 * kw) * 32 + c4];
                float4 w1 = ((const float4*)Wp)[(2 * kw + 1) * 32 + c4];
                uint4 u;
                u.x = pack_bf16(w0.x, w1.x);
                u.y = pack_bf16(w0.y, w1.y);
                u.z = pack_bf16(w0.z, w1.z);
                u.w = pack_bf16(w0.w, w1.w);
                int off = (c4 * 4 + ((kw & 3) << 3)) & 127;
                *(uint4*)(sB + kw * 128 + off) = u;
            }
        }

        // Store prefetched A chunk as pre-scaled bf16x2
        {
            const float s = (c < 4) ? rds : 1.f;
            uint4 u;
            u.x = pack_bf16(pva.x * s, pva.y * s);
            u.y = pack_bf16(pva.z * s, pva.w * s);
            u.z = pack_bf16(pvb.x * s, pvb.y * s);
            u.w = pack_bf16(pvb.z * s, pvb.w * s);
            *(uint4*)(sA + srow * A_STRIDE + wq * 4) = u;
        }

        // Prefetch next chunk (overlaps with mma loop below)
        if (c < 7) {
            const float* An = (c + 1 < 4) ? (const float*)g_agg : x;
            const int ch = (c + 1) & 3;
            pva = make_float4(0.f, 0.f, 0.f, 0.f);
            pvb = make_float4(0.f, 0.f, 0.f, 0.f);
            if (gv) {
                pva = ((const float4*)An)[(size_t)grow * 32 + ch * 8 + wq * 2];
                pvb = ((const float4*)An)[(size_t)grow * 32 + ch * 8 + wq * 2 + 1];
            }
        }
        __syncthreads();   // A (and B) staged

#pragma unroll
        for (int q = 0; q < 2; q++) {           // 2 k16-steps per 32-k chunk
            const int ks = (c & 3) * 2 + q;     // k-step within pass (0..7)
            const int aw = q * 8 + tig;         // A word col in chunk
            unsigned a00 = sA[(rbase)      * A_STRIDE + aw];
            unsigned a01 = sA[(rbase + 8)  * A_STRIDE + aw];
            unsigned a02 = sA[(rbase)      * A_STRIDE + aw + 4];
            unsigned a03 = sA[(rbase + 8)  * A_STRIDE + aw + 4];
            unsigned a10 = sA[(rbase + 16) * A_STRIDE + aw];
            unsigned a11 = sA[(rbase + 24) * A_STRIDE + aw];
            unsigned a12 = sA[(rbase + 16) * A_STRIDE + aw + 4];
            unsigned a13 = sA[(rbase + 24) * A_STRIDE + aw + 4];
            const unsigned* pb = sB + (ks * 8 + tig) * 128;
#pragma unroll
            for (int nt = 0; nt < 4; nt++) {
                int col = (bbase + nt * 8) & 127;
                unsigned b0 = pb[col];
                unsigned b1 = pb[512 + col];    // word-row +4
                mma_bf16(acc[nt],     a00, a01, a02, a03, b0, b1);
                mma_bf16(acc[4 + nt], a10, a11, a12, a13, b0, b1);
            }
        }
    }

    const float res = resp[0];
    const float jw = jwp ? jwp[0] : 0.f;
#pragma unroll
    for (int mt = 0; mt < 2; mt++) {
        const int r0 = blockIdx.x * 64 + mw * 32 + mt * 16 + grp;
        const int r1 = r0 + 8;
        const bool v0 = r0 < n, v1 = r1 < n;
#pragma unroll
        for (int nt = 0; nt < 4; nt++) {
            const int cc = nw * 32 + nt * 8 + tig * 2;
            const float* a = acc[mt * 4 + nt];
            if (v0) {
                float2 xv = *(const float2*)(x + (size_t)r0 * 128 + cc);
                float o0 = xv.x + res * tanhf(a[0]);
                float o1 = xv.y + res * tanhf(a[1]);
                if (jumpbuf) {
                    float2 jv = *(const float2*)(jumpbuf + (size_t)r0 * 128 + cc);
                    o0 += jw * jv.x; o1 += jw * jv.y;
                }
                *(float2*)(out + (size_t)r0 * 128 + cc) = make_float2(o0, o1);
            }
            if (v1) {
                float2 xv = *(const float2*)(x + (size_t)r1 * 128 + cc);
                float o0 = xv.x + res * tanhf(a[2]);
                float o1 = xv.y + res * tanhf(a[3]);
                if (jumpbuf) {
                    float2 jv = *(const float2*)(jumpbuf + (size_t)r1 * 128 + cc);
                    o0 += jw * jv.x; o1 += jw * jv.y;
                }
                *(float2*)(out + (size_t)r1 * 128 + cc) = make_float2(o0, o1);
            }
        }
    }

    // Zero this warp's agg region for layer 2 (32 rows x 32 cols, exclusive)
    if (zeroAgg) {
        int zr = blockIdx.x * 64 + mw * 32 + lane;
        if (zr < n) {
            float4* p = (float4*)(g_agg + (size_t)zr * 128 + nw * 32);
            float4 z = make_float4(0.f, 0.f, 0.f, 0.f);
#pragma unroll
            for (int q = 0; q < 8; q++) p[q] = z;
        }
    }
}

// ---------------------------------------------------------------------------
// Launch sequence (graph-capturable: kernel launches only)
// ---------------------------------------------------------------------------
extern "C" void kernel_launch(void* const* d_in, const int* in_sizes, int n_in,
                              void* d_out, int out_size) {
    const float* emb    = (const float*)d_in[0];
    const float* change = (const float*)d_in[1];
    const float* W1     = (const float*)d_in[2];
    const float* Wl1    = (const float*)d_in[3];
    const float* rel1   = (const float*)d_in[4];
    const float* W2     = (const float*)d_in[5];
    const float* Wl2    = (const float*)d_in[6];
    const float* rel2   = (const float*)d_in[7];
    const float* res    = (const float*)d_in[8];
    const float* jw     = (const float*)d_in[9];
    const float* ewj    = (const float*)d_in[10];
    const int*   ei     = (const int*)d_in[11];
    const int*   et     = (const int*)d_in[12];
    const int*   ej     = (const int*)d_in[13];

    const int N  = in_sizes[0] / 128;
    const int E  = in_sizes[12];
    const int EJ = in_sizes[10];
    if (N <= 0 || E <= 0 || EJ <= 0) return;

    float* out  = (float*)d_out;
    float* outD = out + (size_t)N * 128;

    float* hptr = nullptr;
    cudaGetSymbolAddress((void**)&hptr, g_h);

    cudaFuncSetAttribute(k_gemm, cudaFuncAttributeMaxDynamicSharedMemorySize, SMEM_BYTES);

    const int nd4 = N * 32;
    k_init<<<(nd4 + 255) / 256, 256>>>(change, out, N);
    // layer-1 scatter (also accumulates deg)
    k_scatter<<<(E + 7) / 8, 256>>>(emb, rel1, ei, et, E, 1);
    // jump diffusion into dchange half (independent of convs)
    k_jump<<<(EJ + 7) / 8, 256>>>(emb, ewj, ej, EJ, outD);
    // layer 1: h1 = emb + res*tanh((agg/deg)@W1 + emb@Wloop1); zero agg for L2
    k_gemm<<<(N + 63) / 64, 256, SMEM_BYTES>>>(emb, W1, Wl1, res,
                                               nullptr, nullptr, hptr, N, 1);
    // layer-2 scatter (deg reused)
    k_scatter<<<(E + 7) / 8, 256>>>(hptr, rel2, ei, et, E, 0);
    // layer 2 + jump combine: dchange = h1 + res*tanh(...) + jw*jump
    k_gemm<<<(N + 63) / 64, 256, SMEM_BYTES>>>(hptr, W2, Wl2, res,
                                               jw, outD, outD, N, 0);
}

// round 13
// speedup vs baseline: 1.5984x; 1.2259x over previous
#include <cuda_runtime.h>
#include <math.h>

#define D 128
#define MAXN 100000
#define MAXE 600000
#define MAXEJ 300000
#define NB 512   // max scan blocks per array (ceil(100000/256)=391)

// Scratch (allocation-free: static __device__ arrays)
__device__ float g_agg[(size_t)MAXN * D];   // aggregation buffer
__device__ float g_h[(size_t)MAXN * D];     // hidden state h1
__device__ int   g_cnt[MAXN];               // conv in-degree
__device__ int   g_cntJ[MAXN];              // jump in-degree
__device__ int   g_rowptr[MAXN];            // conv CSR row starts
__device__ int   g_rowptrJ[MAXN];           // jump CSR row starts
__device__ int   g_cur[MAXN];               // permute cursors
__device__ int   g_curJ[MAXN];
__device__ int   g_bsum[2][NB];             // scan block sums
__device__ int   g_epack[MAXE];             // src | (type<<20)
__device__ int2  g_jpack[MAXEJ];            // (src, float bits of weight)

// ---------------------------------------------------------------------------
// K0: copy change -> out[0:ND]; zero degree counters
// ---------------------------------------------------------------------------
__global__ void k_init(const float* __restrict__ change, float* __restrict__ out, int n) {
    int i = blockIdx.x * blockDim.x + threadIdx.x;
    int nd4 = n * (D / 4);
    if (i < nd4) ((float4*)out)[i] = ((const float4*)change)[i];
    if (i < n) { g_cnt[i] = 0; g_cntJ[i] = 0; }
}

// ---------------------------------------------------------------------------
// Histogram of destinations (conv + jump)
// ---------------------------------------------------------------------------
__global__ void k_hist(const int* __restrict__ ei, const int* __restrict__ ej,
                       int E, int EJ) {
    int i = blockIdx.x * blockDim.x + threadIdx.x;
    if (i < E)  atomicAdd(&g_cnt[ei[E + i]], 1);
    if (i < EJ) atomicAdd(&g_cntJ[ej[EJ + i]], 1);
}

// ---------------------------------------------------------------------------
// Exclusive scan, 3 kernels, blockIdx.y selects conv(0)/jump(1) array
// ---------------------------------------------------------------------------
__global__ void k_scan1(int n) {
    __shared__ int s[256];
    const int y = blockIdx.y;
    const int* cnt = y ? g_cntJ : g_cnt;
    int* rp = y ? g_rowptrJ : g_rowptr;
    int idx = blockIdx.x * 256 + threadIdx.x;
    int v = (idx < n) ? cnt[idx] : 0;
    s[threadIdx.x] = v;
#pragma unroll
    for (int off = 1; off < 256; off <<= 1) {
        __syncthreads();
        int t = (threadIdx.x >= off) ? s[threadIdx.x - off] : 0;
        __syncthreads();
        s[threadIdx.x] += t;
    }
    __syncthreads();
    if (idx < n) rp[idx] = s[threadIdx.x] - v;
    if (threadIdx.x == 255) g_bsum[y][blockIdx.x] = s[255];
}

__global__ void k_scan2(int nb) {
    __shared__ int s[512];
    const int y = blockIdx.y;
    int v = (threadIdx.x < nb) ? g_bsum[y][threadIdx.x] : 0;
    s[threadIdx.x] = v;
#pragma unroll
    for (int off = 1; off < 512; off <<= 1) {
        __syncthreads();
        int t = (threadIdx.x >= off) ? s[threadIdx.x - off] : 0;
        __syncthreads();
        s[threadIdx.x] += t;
    }
    __syncthreads();
    if (threadIdx.x < nb) g_bsum[y][threadIdx.x] = s[threadIdx.x] - v;
}

__global__ void k_scan3(int n) {
    const int y = blockIdx.y;
    int* rp = y ? g_rowptrJ : g_rowptr;
    int* cur = y ? g_curJ : g_cur;
    int idx = blockIdx.x * 256 + threadIdx.x;
    if (idx < n) {
        int v = rp[idx] + g_bsum[y][blockIdx.x];
        rp[idx] = v;
        cur[idx] = v;
    }
}

// ---------------------------------------------------------------------------
// Permute edges into CSR order (conv: packed src|type; jump: src + weight)
// ---------------------------------------------------------------------------
__global__ void k_permute(const int* __restrict__ ei, const int* __restrict__ et,
                          const int* __restrict__ ej, const float* __restrict__ w,
                          int E, int EJ) {
    int i = blockIdx.x * blockDim.x + threadIdx.x;
    if (i < E) {
        int dst = ei[E + i];
        int pos = atomicAdd(&g_cur[dst], 1);
        g_epack[pos] = ei[i] | (et[i] << 20);
    }
    if (i < EJ) {
        int dst = ej[EJ + i];
        int pos = atomicAdd(&g_curJ[dst], 1);
        g_jpack[pos] = make_int2(ej[i], __float_as_int(w[i]));
    }
}

// ---------------------------------------------------------------------------
// Conv aggregation, pull-style: one warp per dst node.
//   agg[v] = sum_{e in in(v)} x[src_e] * rel[type_e]   (single write, no atomics)
// ---------------------------------------------------------------------------
__global__ void k_agg(const float* __restrict__ x, const float* __restrict__ rel,
                      int n) {
    int v = blockIdx.x * 8 + (threadIdx.x >> 5);
    int lane = threadIdx.x & 31;
    if (v >= n) return;
    int start = g_rowptr[v];
    int deg = g_cnt[v];
    float4 acc = make_float4(0.f, 0.f, 0.f, 0.f);
    for (int base = 0; base < deg; base += 32) {
        int rem = deg - base;
        int cntc = rem < 32 ? rem : 32;
        int m = (lane < cntc) ? g_epack[start + base + lane] : 0;
        for (int j = 0; j < cntc; j++) {
            int pm = __shfl_sync(0xffffffffu, m, j);
            int src = pm & 0xFFFFF;
            int t = ((unsigned)pm) >> 20;
            float4 xv = ((const float4*)x)[(size_t)src * 32 + lane];
            float4 rv = ((const float4*)rel)[(size_t)t * 32 + lane];
            acc.x += xv.x * rv.x; acc.y += xv.y * rv.y;
            acc.z += xv.z * rv.z; acc.w += xv.w * rv.w;
        }
    }
    ((float4*)g_agg)[(size_t)v * 32 + lane] = acc;
}

// ---------------------------------------------------------------------------
// Jump aggregation, pull-style: outD[v] = sum w_e * emb[src_e]
// ---------------------------------------------------------------------------
__global__ void k_aggj(const float* __restrict__ emb, float* __restrict__ outD,
                       int n) {
    int v = blockIdx.x * 8 + (threadIdx.x >> 5);
    int lane = threadIdx.x & 31;
    if (v >= n) return;
    int start = g_rowptrJ[v];
    int deg = g_cntJ[v];
    float4 acc = make_float4(0.f, 0.f, 0.f, 0.f);
    for (int base = 0; base < deg; base += 32) {
        int rem = deg - base;
        int cntc = rem < 32 ? rem : 32;
        int2 m = (lane < cntc) ? g_jpack[start + base + lane] : make_int2(0, 0);
        for (int j = 0; j < cntc; j++) {
            int src = __shfl_sync(0xffffffffu, m.x, j);
            float wv = __int_as_float(__shfl_sync(0xffffffffu, m.y, j));
            float4 xv = ((const float4*)emb)[(size_t)src * 32 + lane];
            acc.x += wv * xv.x; acc.y += wv * xv.y;
            acc.z += wv * xv.z; acc.w += wv * xv.w;
        }
    }
    ((float4*)outD)[(size_t)v * 32 + lane] = acc;
}

// ---------------------------------------------------------------------------
// Fused layer GEMM (bf16 mma.sync m16n8k16) — unchanged from R10 except
// deg comes from g_cnt (int) and the agg-zeroing epilogue is gone.
// ---------------------------------------------------------------------------
#define A_STRIDE 20
#define SMEM_WORDS (64 * 128 + 64 * A_STRIDE)
#define SMEM_BYTES (SMEM_WORDS * 4)

__device__ __forceinline__ unsigned pack_bf16(float lo, float hi) {
    unsigned r;
    asm("cvt.rn.bf16x2.f32 %0, %1, %2;" : "=r"(r) : "f"(hi), "f"(lo));
    return r;
}

__device__ __forceinline__ void mma_bf16(float* c, unsigned a0, unsigned a1,
                                         unsigned a2, unsigned a3,
                                         unsigned b0, unsigned b1) {
    asm("mma.sync.aligned.m16n8k16.row.col.f32.bf16.bf16.f32 "
        "{%0,%1,%2,%3}, {%4,%5,%6,%7}, {%8,%9}, {%0,%1,%2,%3};"
        : "+f"(c[0]), "+f"(c[1]), "+f"(c[2]), "+f"(c[3])
        : "r"(a0), "r"(a1), "r"(a2), "r"(a3), "r"(b0), "r"(b1));
}

__global__ __launch_bounds__(256, 3)
void k_gemm(const float* __restrict__ x, const float* __restrict__ W,
            const float* __restrict__ Wl, const float* __restrict__ resp,
            const float* __restrict__ jwp, const float* __restrict__ jumpbuf,
            float* __restrict__ out, int n) {
    extern __shared__ unsigned sB[];            // B: words [0, 8192) bf16x2
    unsigned* sA = sB + 64 * 128;               // A: [64][20] bf16x2 words

    const int tid = threadIdx.x;
    const int warp = tid >> 5, lane = tid & 31;
    const int grp = lane >> 2, tig = lane & 3;
    const int mw = warp >> 2;        // 0..1  (m half: 32 rows)
    const int nw = warp & 3;         // 0..3  (n quarter: 32 cols)
    const int rbase = mw * 32 + grp;

    const int srow = tid >> 2, wq = tid & 3;
    const int grow = blockIdx.x * 64 + srow;
    const bool gv = grow < n;
    float rds = 0.f;
    if (gv) rds = 1.0f / fmaxf((float)g_cnt[grow], 1.0f);

    float acc[8][4];
#pragma unroll
    for (int i = 0; i < 8; i++)
#pragma unroll
        for (int q = 0; q < 4; q++) acc[i][q] = 0.f;

    const int bbase = nw * 32 + grp + tig * 8;

    float4 pva = make_float4(0.f, 0.f, 0.f, 0.f);
    float4 pvb = make_float4(0.f, 0.f, 0.f, 0.f);
    if (gv) {
        pva = ((const float4*)g_agg)[(size_t)grow * 32 + wq * 2];
        pvb = ((const float4*)g_agg)[(size_t)grow * 32 + wq * 2 + 1];
    }

#pragma unroll 1
    for (int c = 0; c < 8; c++) {
        __syncthreads();

        if (c == 0 || c == 4) {
            const float* Wp = (c == 0) ? W : Wl;
#pragma unroll
            for (int t = 0; t < 8; t++) {
                int j = tid + t * 256;
                int kw = j >> 5, c4 = j & 31;
                float4 w0 = ((const float4*)Wp)[(2 * kw) * 32 + c4];
                float4 w1 = ((const float4*)Wp)[(2 * kw + 1) * 32 + c4];
                uint4 u;
                u.x = pack_bf16(w0.x, w1.x);
                u.y = pack_bf16(w0.y, w1.y);
                u.z = pack_bf16(w0.z, w1.z);
                u.w = pack_bf16(w0.w, w1.w);
                int off = (c4 * 4 + ((kw & 3) << 3)) & 127;
                *(uint4*)(sB + kw * 128 + off) = u;
            }
        }

        {
            const float s = (c < 4) ? rds : 1.f;
            uint4 u;
            u.x = pack_bf16(pva.x * s, pva.y * s);
            u.y = pack_bf16(pva.z * s, pva.w * s);
            u.z = pack_bf16(pvb.x * s, pvb.y * s);
            u.w = pack_bf16(pvb.z * s, pvb.w * s);
            *(uint4*)(sA + srow * A_STRIDE + wq * 4) = u;
        }

        if (c < 7) {
            const float* An = (c + 1 < 4) ? (const float*)g_agg : x;
            const int ch = (c + 1) & 3;
            pva = make_float4(0.f, 0.f, 0.f, 0.f);
            pvb = make_float4(0.f, 0.f, 0.f, 0.f);
            if (gv) {
                pva = ((const float4*)An)[(size_t)grow * 32 + ch * 8 + wq * 2];
                pvb = ((const float4*)An)[(size_t)grow * 32 + ch * 8 + wq * 2 + 1];
            }
        }
        __syncthreads();

#pragma unroll
        for (int q = 0; q < 2; q++) {
            const int ks = (c & 3) * 2 + q;
            const int aw = q * 8 + tig;
            unsigned a00 = sA[(rbase)      * A_STRIDE + aw];
            unsigned a01 = sA[(rbase + 8)  * A_STRIDE + aw];
            unsigned a02 = sA[(rbase)      * A_STRIDE + aw + 4];
            unsigned a03 = sA[(rbase + 8)  * A_STRIDE + aw + 4];
            unsigned a10 = sA[(rbase + 16) * A_STRIDE + aw];
            unsigned a11 = sA[(rbase + 24) * A_STRIDE + aw];
            unsigned a12 = sA[(rbase + 16) * A_STRIDE + aw + 4];
            unsigned a13 = sA[(rbase + 24) * A_STRIDE + aw + 4];
            const unsigned* pb = sB + (ks * 8 + tig) * 128;
#pragma unroll
            for (int nt = 0; nt < 4; nt++) {
                int col = (bbase + nt * 8) & 127;
                unsigned b0 = pb[col];
                unsigned b1 = pb[512 + col];
                mma_bf16(acc[nt],     a00, a01, a02, a03, b0, b1);
                mma_bf16(acc[4 + nt], a10, a11, a12, a13, b0, b1);
            }
        }
    }

    const float res = resp[0];
    const float jw = jwp ? jwp[0] : 0.f;
#pragma unroll
    for (int mt = 0; mt < 2; mt++) {
        const int r0 = blockIdx.x * 64 + mw * 32 + mt * 16 + grp;
        const int r1 = r0 + 8;
        const bool v0 = r0 < n, v1 = r1 < n;
#pragma unroll
        for (int nt = 0; nt < 4; nt++) {
            const int cc = nw * 32 + nt * 8 + tig * 2;
            const float* a = acc[mt * 4 + nt];
            if (v0) {
                float2 xv = *(const float2*)(x + (size_t)r0 * 128 + cc);
                float o0 = xv.x + res * tanhf(a[0]);
                float o1 = xv.y + res * tanhf(a[1]);
                if (jumpbuf) {
                    float2 jv = *(const float2*)(jumpbuf + (size_t)r0 * 128 + cc);
                    o0 += jw * jv.x; o1 += jw * jv.y;
                }
                *(float2*)(out + (size_t)r0 * 128 + cc) = make_float2(o0, o1);
            }
            if (v1) {
                float2 xv = *(const float2*)(x + (size_t)r1 * 128 + cc);
                float o0 = xv.x + res * tanhf(a[2]);
                float o1 = xv.y + res * tanhf(a[3]);
                if (jumpbuf) {
                    float2 jv = *(const float2*)(jumpbuf + (size_t)r1 * 128 + cc);
                    o0 += jw * jv.x; o1 += jw * jv.y;
                }
                *(float2*)(out + (size_t)r1 * 128 + cc) = make_float2(o0, o1);
            }
        }
    }
}

// ---------------------------------------------------------------------------
// Launch sequence (graph-capturable: kernel launches only)
// ---------------------------------------------------------------------------
extern "C" void kernel_launch(void* const* d_in, const int* in_sizes, int n_in,
                              void* d_out, int out_size) {
    const float* emb    = (const float*)d_in[0];
    const float* change = (const float*)d_in[1];
    const float* W1     = (const float*)d_in[2];
    const float* Wl1    = (const float*)d_in[3];
    const float* rel1   = (const float*)d_in[4];
    const float* W2     = (const float*)d_in[5];
    const float* Wl2    = (const float*)d_in[6];
    const float* rel2   = (const float*)d_in[7];
    const float* res    = (const float*)d_in[8];
    const float* jw     = (const float*)d_in[9];
    const float* ewj    = (const float*)d_in[10];
    const int*   ei     = (const int*)d_in[11];
    const int*   et     = (const int*)d_in[12];
    const int*   ej     = (const int*)d_in[13];

    const int N  = in_sizes[0] / 128;
    const int E  = in_sizes[12];
    const int EJ = in_sizes[10];
    if (N <= 0 || E <= 0 || EJ <= 0) return;

    float* out  = (float*)d_out;
    float* outD = out + (size_t)N * 128;

    float* hptr = nullptr;
    cudaGetSymbolAddress((void**)&hptr, g_h);

    cudaFuncSetAttribute(k_gemm, cudaFuncAttributeMaxDynamicSharedMemorySize, SMEM_BYTES);

    const int nd4 = N * 32;
    const int emax = E > EJ ? E : EJ;
    const int nb = (N + 255) / 256;
    dim3 gscan(nb, 2);

    // CSR build (once; conv CSR reused by both layers)
    k_init<<<(nd4 + 255) / 256, 256>>>(change, out, N);
    k_hist<<<(emax + 255) / 256, 256>>>(ei, ej, E, EJ);
    k_scan1<<<gscan, 256>>>(N);
    k_scan2<<<dim3(1, 2), 512>>>(nb);
    k_scan3<<<gscan, 256>>>(N);
    k_permute<<<(emax + 255) / 256, 256>>>(ei, et, ej, ewj, E, EJ);

    const int aggBlocks = (N + 7) / 8;
    // layer-1 aggregation + jump aggregation (both read emb)
    k_agg<<<aggBlocks, 256>>>(emb, rel1, N);
    k_aggj<<<aggBlocks, 256>>>(emb, outD, N);
    // layer 1: h1 = emb + res*tanh((agg/deg)@W1 + emb@Wloop1)
    k_gemm<<<(N + 63) / 64, 256, SMEM_BYTES>>>(emb, W1, Wl1, res,
                                               nullptr, nullptr, hptr, N);
    // layer-2 aggregation (CSR reused)
    k_agg<<<aggBlocks, 256>>>(hptr, rel2, N);
    // layer 2 + jump combine: dchange = h1 + res*tanh(...) + jw*jump
    k_gemm<<<(N + 63) / 64, 256, SMEM_BYTES>>>(hptr, W2, Wl2, res,
                                               jw, outD, outD, N);
}